// round 14
// baseline (speedup 1.0000x reference)
#include <cuda_runtime.h>
#include <cstdint>
#include <math.h>

#define N_ROWS 4096
#define C_CLS  91
#define R_ROI  1024
#define K_KP   17
#define HM     56
#define RESO   64
#define BETA   (1.0f/9.0f)

#define OFF_XY   2
#define OFF_ES   (2 + R_ROI*K_KP*3)            /* 52226 */
#define OFF_MASK (OFF_ES + R_ROI*K_KP)         /* 69634 */
#define MASK_HW  784

#define MAPS_PER_CTA 4
#define KP_BLOCKS   (R_ROI * K_KP / MAPS_PER_CTA)  /* 4352 */
#define MASK_F4     (R_ROI * MASK_HW / 4)      /* 200704 float4 loads */
#define MASK_BLOCKS (MASK_F4 / 256)            /* 784 */
#define LOSS_BLOCKS 64
#define TOTAL_BLOCKS (LOSS_BLOCKS + MASK_BLOCKS + KP_BLOCKS)

#define SROW 60                                 /* padded row stride (floats) */

__device__ float g_partials[2 * LOSS_BLOCKS];
__device__ int   g_done = 0;

// ---------------------------------------------------------------------------
// Compile-time bicubic 56->64 resample parameters (jax.image.resize
// semantics: half-pixel sampling, Keys a=-0.5, OOB taps dropped + renorm).
// s(xo) = (14*xo - 1)/16 exactly.
// ---------------------------------------------------------------------------
__host__ __device__ constexpr int qp_floor(int xo) {
    int num = 14 * xo - 1;
    return (num >= 0) ? num / 16 : -((-num + 15) / 16);
}
__host__ __device__ constexpr int qp_base(int xo) {
    int b = qp_floor(xo) - 1;
    return (b < 0) ? 0 : ((b > HM - 4) ? (HM - 4) : b);
}
__host__ __device__ constexpr int qp_W(int Q)  { return Q==0?0 : Q==1?12 : Q==2?24 : 40; }
__host__ __device__ constexpr int qp_NL(int Q) { return (Q==1 || Q==2) ? 5 : 4; }
__host__ __device__ constexpr int qp_S(int Q, int j) { return qp_base(16*Q + j) - qp_W(Q); }

__host__ __device__ constexpr float qp_cubic(int dn16) {   // t = |dn16|/16
    float t = (float)(dn16 < 0 ? -dn16 : dn16) / 16.0f;
    return (t < 1.0f) ? ((1.5f*t - 2.5f)*t)*t + 1.0f
         : (t < 2.0f) ? ((-0.5f*t + 2.5f)*t - 4.0f)*t + 2.0f
         : 0.0f;
}
__host__ __device__ constexpr float qp_wsum(int xo) {
    float s = 0.f;
    for (int k = qp_floor(xo) - 1; k <= qp_floor(xo) + 2; ++k)
        if (k >= 0 && k < HM) s += qp_cubic(14*xo - 1 - 16*k);
    return s;
}
__host__ __device__ constexpr float qp_wt(int xo, int slot) {
    int k = qp_base(xo) + slot;
    if (k < qp_floor(xo) - 1 || k > qp_floor(xo) + 2 || k < 0 || k >= HM)
        return 0.0f;
    return qp_cubic(14*xo - 1 - 16*k) * (1.0f / qp_wsum(xo));
}

// C++11-safe compile-time for.
template<int J, int N> struct SFor {
    template<typename F> __device__ __forceinline__ static void run(F&& f) {
        f(J_tag()); SFor<J+1, N>::run(f);
    }
    struct J_tag { static constexpr int value = J; };
};
template<int N> struct SFor<N, N> {
    template<typename F> __device__ __forceinline__ static void run(F&&) {}
};

// Interpolate 16 consecutive outputs (xo = 16Q..16Q+15) of one line.
// All weights are FFMA immediates.
template<int Q, typename F>
__device__ __forceinline__ void interp16(const float* __restrict__ row, F emit)
{
    float4 win4[qp_NL(Q)];
    #pragma unroll
    for (int i = 0; i < qp_NL(Q); i++)
        win4[i] = *(const float4*)(row + qp_W(Q) + 4*i);
    const float* win = (const float*)win4;
    SFor<0, 16>::run([&](auto jc) {
        constexpr int   j  = decltype(jc)::value;
        constexpr int   s  = qp_S(Q, j);
        constexpr int   xo = 16*Q + j;
        constexpr float w0 = qp_wt(xo, 0), w1 = qp_wt(xo, 1);
        constexpr float w2 = qp_wt(xo, 2), w3 = qp_wt(xo, 3);
        float v = fmaf(w0, win[s],
                  fmaf(w1, win[s+1],
                  fmaf(w2, win[s+2], w3 * win[s+3])));
        emit(j, v);
    });
}

// ---------------------------------------------------------------------------
// Keypoint multi-map block: 4 maps per CTA, DOUBLE-buffered map smem.
// Prefetch of map m+1 is issued at the top of map m, overlapping the whole
// compute of map m. 2 barriers/map; epilogue deferred (parity swv/swi).
// ---------------------------------------------------------------------------
__device__ __forceinline__ void kp_multi(
    int map_base, const float* __restrict__ maps, const float* __restrict__ rois,
    float* __restrict__ out)
{
    __shared__ __align__(16) float bufA[HM * SROW];   // 13440 B
    __shared__ __align__(16) float bufB[HM * SROW];   // 13440 B
    __shared__ __align__(16) float tmpT[RESO * SROW]; // 15360 B ([xo][y])
    __shared__ float swv[2][8];
    __shared__ int   swi[2][8];

    const int tid = threadIdx.x;
    const int lane_o = tid & 63;
    const int q      = tid >> 6;              // warp-uniform

    // Per-thread staging slots (idx < 784): dst smem offsets, computed once.
    int  s_y0 = (tid)        / 14, s_c0 = (tid)        - s_y0 * 14;
    int  s_y1 = (tid + 256)  / 14, s_c1 = (tid + 256)  - s_y1 * 14;
    int  s_y2 = (tid + 512)  / 14, s_c2 = (tid + 512)  - s_y2 * 14;
    bool has3 = (tid + 768) < 784;            // tid < 16
    int  s_y3 = (tid + 768)  / 14, s_c3 = (tid + 768)  - s_y3 * 14;
    int  o0 = s_y0 * SROW + 4*s_c0, o1 = s_y1 * SROW + 4*s_c1;
    int  o2 = s_y2 * SROW + 4*s_c2, o3 = s_y3 * SROW + 4*s_c3;
    unsigned dA0 = (unsigned)__cvta_generic_to_shared(bufA + o0);
    unsigned dA1 = (unsigned)__cvta_generic_to_shared(bufA + o1);
    unsigned dA2 = (unsigned)__cvta_generic_to_shared(bufA + o2);
    unsigned dA3 = (unsigned)__cvta_generic_to_shared(bufA + o3);
    unsigned dB0 = (unsigned)__cvta_generic_to_shared(bufB + o0);
    unsigned dB1 = (unsigned)__cvta_generic_to_shared(bufB + o1);
    unsigned dB2 = (unsigned)__cvta_generic_to_shared(bufB + o2);
    unsigned dB3 = (unsigned)__cvta_generic_to_shared(bufB + o3);

    auto stage_load = [&](int mid, bool toB) {
        const char* src = (const char*)(maps + (size_t)mid * (HM * HM));
        unsigned e0 = toB ? dB0 : dA0, e1 = toB ? dB1 : dA1;
        unsigned e2 = toB ? dB2 : dA2, e3 = toB ? dB3 : dA3;
        asm volatile("cp.async.cg.shared.global [%0], [%1], 16;"
                     :: "r"(e0), "l"(src + (size_t)tid * 16) : "memory");
        asm volatile("cp.async.cg.shared.global [%0], [%1], 16;"
                     :: "r"(e1), "l"(src + (size_t)(tid + 256) * 16) : "memory");
        asm volatile("cp.async.cg.shared.global [%0], [%1], 16;"
                     :: "r"(e2), "l"(src + (size_t)(tid + 512) * 16) : "memory");
        if (has3)
            asm volatile("cp.async.cg.shared.global [%0], [%1], 16;"
                         :: "r"(e3), "l"(src + (size_t)(tid + 768) * 16) : "memory");
        asm volatile("cp.async.commit_group;" ::: "memory");
    };

    stage_load(map_base, false);               // map 0 -> bufA
    asm volatile("cp.async.wait_group 0;" ::: "memory");
    __syncthreads();

    #pragma unroll 1
    for (int m = 0; m < MAPS_PER_CTA; m++) {
        const int map_id = map_base + m;
        const int par = m & 1;
        const float* cur = par ? bufB : bufA;

        // Prefetch next map into the other buffer (free since map m-1's
        // stage-1 barrier). Overlaps the WHOLE compute of map m.
        if (m + 1 < MAPS_PER_CTA) stage_load(map_base + m + 1, par == 0);

        // Stage 1: x-interp, transposed store tmpT[xo*SROW + y].
        if (lane_o < HM) {
            const float* row = cur + lane_o * SROW;
            float* tc = tmpT + lane_o;
            switch (q) {
            case 0: interp16<0>(row, [&](int j, float v){ tc[(   j)*SROW] = v; }); break;
            case 1: interp16<1>(row, [&](int j, float v){ tc[(16+j)*SROW] = v; }); break;
            case 2: interp16<2>(row, [&](int j, float v){ tc[(32+j)*SROW] = v; }); break;
            default:interp16<3>(row, [&](int j, float v){ tc[(48+j)*SROW] = v; }); break;
            }
        }
        __syncthreads();                       // tmpT ready; cur reads done

        // Stage 2: y-interp + fused argmax (track j only; p built once).
        float best = -INFINITY; int bj = 0;
        {
            const float* row = tmpT + lane_o * SROW;
            switch (q) {
            case 0: interp16<0>(row, [&](int j, float v){
                        if (v > best) { best = v; bj = j; } }); break;
            case 1: interp16<1>(row, [&](int j, float v){
                        if (v > best) { best = v; bj = j; } }); break;
            case 2: interp16<2>(row, [&](int j, float v){
                        if (v > best) { best = v; bj = j; } }); break;
            default:interp16<3>(row, [&](int j, float v){
                        if (v > best) { best = v; bj = j; } }); break;
            }
        }
        int bidx = ((16*q + bj) << 6) | lane_o;   // p = yo*64 + xo

        #pragma unroll
        for (int o = 16; o; o >>= 1) {
            float ov = __shfl_xor_sync(0xffffffffu, best, o);
            int   oi = __shfl_xor_sync(0xffffffffu, bidx, o);
            if (ov > best || (ov == best && oi < bidx)) { best = ov; bidx = oi; }
        }
        if ((tid & 31) == 0) { swv[par][tid >> 5] = best; swi[par][tid >> 5] = bidx; }

        asm volatile("cp.async.wait_group 0;" ::: "memory");
        __syncthreads();   // next buffer ready; swv[par] visible; tmpT free

        // Deferred epilogue: overlaps next map's stage 1. Same-parity swv
        // write is 2 maps (2 barriers) away -> race-free.
        if (tid == 0) {
            #pragma unroll
            for (int i = 1; i < 8; i++) {
                if (swv[par][i] > best ||
                    (swv[par][i] == best && swi[par][i] < bidx)) {
                    best = swv[par][i]; bidx = swi[par][i];
                }
            }
            int r = map_id / K_KP;
            const float* rp = rois + r * 4;
            float x1 = rp[0], y1 = rp[1], x2 = rp[2], y2 = rp[3];
            float wc = fmaxf(x2 - x1, 1.f) * (1.f / (float)RESO);
            float hc = fmaxf(y2 - y1, 1.f) * (1.f / (float)RESO);
            int xi = bidx & 63, yi = bidx >> 6;
            float* xy = out + OFF_XY + (size_t)map_id * 3;
            xy[0] = (xi + 0.5f) * wc + x1;
            xy[1] = (yi + 0.5f) * hc + y1;
            xy[2] = 1.f;
            out[OFF_ES + map_id] = best;
        }
    }
}

// ---------------------------------------------------------------------------
// Mask inference: float4 gather, fast sigmoid, float2 stores (OFF_MASK is
// only 8B-aligned in the output).
// ---------------------------------------------------------------------------
__device__ __forceinline__ void mask_block(
    int mb, const float* __restrict__ mlog, const int* __restrict__ mlab,
    float* __restrict__ out)
{
    int idx = mb * 256 + threadIdx.x;          // float4 index < MASK_F4
    int r = idx / (MASK_HW / 4);
    int i = idx - r * (MASK_HW / 4);
    int lab = __ldg(&mlab[r]);
    float4 v = __ldg((const float4*)mlog + ((size_t)r * C_CLS + lab) * (MASK_HW / 4) + i);
    float2* o2 = (float2*)(out + OFF_MASK) + idx * 2;
    float2 a, b;
    a.x = __fdividef(1.f, 1.f + __expf(-v.x));
    a.y = __fdividef(1.f, 1.f + __expf(-v.y));
    b.x = __fdividef(1.f, 1.f + __expf(-v.z));
    b.y = __fdividef(1.f, 1.f + __expf(-v.w));
    o2[0] = a;
    o2[1] = b;
}

// ---------------------------------------------------------------------------
// FastRCNN loss partial block + last-block final reduction (deterministic).
// ---------------------------------------------------------------------------
__device__ __forceinline__ void loss_block(
    int lb, const float* __restrict__ logits, const float* __restrict__ br,
    const int* __restrict__ labels, const float* __restrict__ tgt,
    float* __restrict__ out)
{
    __shared__ float scls[8], sbox[8];
    __shared__ int   is_last;
    int lane  = threadIdx.x & 31;
    int wid   = threadIdx.x >> 5;
    int gwarp = lb * 8 + wid;
    const int nwarps = LOSS_BLOCKS * 8;

    float cls_acc = 0.f, box_acc = 0.f;
    for (int row = gwarp; row < N_ROWS; row += nwarps) {
        const float* lp = logits + (size_t)row * C_CLS;
        int lab = labels[row];
        float v0 = (lane      < C_CLS) ? lp[lane]      : -INFINITY;
        float v1 = (lane + 32 < C_CLS) ? lp[lane + 32] : -INFINITY;
        float v2 = (lane + 64 < C_CLS) ? lp[lane + 64] : -INFINITY;
        float m = fmaxf(v0, fmaxf(v1, v2));
        #pragma unroll
        for (int o = 16; o; o >>= 1) m = fmaxf(m, __shfl_xor_sync(0xffffffffu, m, o));
        float s = 0.f;
        if (lane      < C_CLS) s += __expf(v0 - m);
        if (lane + 32 < C_CLS) s += __expf(v1 - m);
        if (lane + 64 < C_CLS) s += __expf(v2 - m);
        #pragma unroll
        for (int o = 16; o; o >>= 1) s += __shfl_xor_sync(0xffffffffu, s, o);
        float lv = -INFINITY;
        if (lane == lab)           lv = v0;
        else if (lane + 32 == lab) lv = v1;
        else if (lane + 64 == lab) lv = v2;
        #pragma unroll
        for (int o = 16; o; o >>= 1) lv = fmaxf(lv, __shfl_xor_sync(0xffffffffu, lv, o));
        cls_acc += (m + __logf(s)) - lv;

        if (lab > 0) {
            float sl = 0.f;
            if (lane < 4) {
                float d  = br[(size_t)row * (C_CLS * 4) + lab * 4 + lane] - tgt[row * 4 + lane];
                float ad = fabsf(d);
                sl = (ad < BETA) ? 0.5f * d * d / BETA : ad - 0.5f * BETA;
            }
            sl += __shfl_xor_sync(0xffffffffu, sl, 1);
            sl += __shfl_xor_sync(0xffffffffu, sl, 2);
            if (lane == 0) box_acc += sl;
        }
    }

    if (lane == 0) { scls[wid] = cls_acc; sbox[wid] = box_acc; }
    __syncthreads();
    if (threadIdx.x == 0) {
        float c = 0.f, b = 0.f;
        #pragma unroll
        for (int i = 0; i < 8; i++) { c += scls[i]; b += sbox[i]; }
        g_partials[lb * 2]     = c;
        g_partials[lb * 2 + 1] = b;
        __threadfence();
        is_last = (atomicAdd(&g_done, 1) == LOSS_BLOCKS - 1);
    }
    __syncthreads();

    if (is_last && threadIdx.x < 32) {
        __threadfence();
        float c = 0.f, b = 0.f;
        for (int i = lane; i < LOSS_BLOCKS; i += 32) {
            c += g_partials[2 * i];
            b += g_partials[2 * i + 1];
        }
        #pragma unroll
        for (int o = 16; o; o >>= 1) {
            c += __shfl_xor_sync(0xffffffffu, c, o);
            b += __shfl_xor_sync(0xffffffffu, b, o);
        }
        if (lane == 0) {
            out[0] = c * (1.f / (float)N_ROWS);
            out[1] = b * (1.f / (float)N_ROWS);
            g_done = 0;                       // reset for next graph replay
        }
    }
}

// ---------------------------------------------------------------------------
// Fused kernel: loss first, then mask, then multi-map kp.
// ---------------------------------------------------------------------------
__global__ void __launch_bounds__(256) fused_kernel(
    const float* __restrict__ logits, const float* __restrict__ br,
    const int*   __restrict__ labels, const float* __restrict__ tgt,
    const float* __restrict__ kp_maps, const float* __restrict__ kp_rois,
    const float* __restrict__ mlog, const int* __restrict__ mlab,
    float* __restrict__ out)
{
    int b = blockIdx.x;
    if (b < LOSS_BLOCKS) {
        loss_block(b, logits, br, labels, tgt, out);
    } else if (b < LOSS_BLOCKS + MASK_BLOCKS) {
        mask_block(b - LOSS_BLOCKS, mlog, mlab, out);
    } else {
        kp_multi((b - (LOSS_BLOCKS + MASK_BLOCKS)) * MAPS_PER_CTA,
                 kp_maps, kp_rois, out);
    }
}

// ---------------------------------------------------------------------------
extern "C" void kernel_launch(void* const* d_in, const int* in_sizes, int n_in,
                              void* d_out, int out_size)
{
    const float* class_logits       = (const float*)d_in[0];
    const float* box_regression     = (const float*)d_in[1];
    const int*   labels             = (const int*)  d_in[2];
    const float* regression_targets = (const float*)d_in[3];
    const float* kp_maps            = (const float*)d_in[4];
    const float* kp_rois            = (const float*)d_in[5];
    const float* mask_logits        = (const float*)d_in[6];
    const int*   mask_labels        = (const int*)  d_in[7];
    float* out = (float*)d_out;

    fused_kernel<<<TOTAL_BLOCKS, 256>>>(class_logits, box_regression, labels,
                                        regression_targets, kp_maps, kp_rois,
                                        mask_logits, mask_labels, out);
}

// round 16
// speedup vs baseline: 1.0633x; 1.0633x over previous
#include <cuda_runtime.h>
#include <cstdint>
#include <math.h>

#define N_ROWS 4096
#define C_CLS  91
#define R_ROI  1024
#define K_KP   17
#define HM     56
#define RESO   64
#define BETA   (1.0f/9.0f)

#define OFF_XY   2
#define OFF_ES   (2 + R_ROI*K_KP*3)            /* 52226 */
#define OFF_MASK (OFF_ES + R_ROI*K_KP)         /* 69634 */
#define MASK_HW  784

#define MAPS_PER_CTA 4
#define KP_BLOCKS   (R_ROI * K_KP / MAPS_PER_CTA)  /* 4352 */
#define MASK_F4     (R_ROI * MASK_HW / 4)      /* 200704 float4 loads */
#define MASK_BLOCKS (MASK_F4 / 256)            /* 784 */
#define LOSS_BLOCKS 64
#define TOTAL_BLOCKS (LOSS_BLOCKS + MASK_BLOCKS + KP_BLOCKS)

#define SROW 60                                 /* padded row stride (floats) */

__device__ float g_partials[2 * LOSS_BLOCKS];
__device__ int   g_done = 0;

// ---------------------------------------------------------------------------
// Compile-time bicubic 56->64 resample parameters (jax.image.resize
// semantics: half-pixel sampling, Keys a=-0.5, OOB taps dropped + renorm).
// s(xo) = (14*xo - 1)/16 exactly.
// ---------------------------------------------------------------------------
__host__ __device__ constexpr int qp_floor(int xo) {
    int num = 14 * xo - 1;
    return (num >= 0) ? num / 16 : -((-num + 15) / 16);
}
__host__ __device__ constexpr int qp_base(int xo) {
    int b = qp_floor(xo) - 1;
    return (b < 0) ? 0 : ((b > HM - 4) ? (HM - 4) : b);
}
__host__ __device__ constexpr int qp_W(int Q)  { return Q==0?0 : Q==1?12 : Q==2?24 : 40; }
__host__ __device__ constexpr int qp_NL(int Q) { return (Q==1 || Q==2) ? 5 : 4; }
__host__ __device__ constexpr int qp_S(int Q, int j) { return qp_base(16*Q + j) - qp_W(Q); }

__host__ __device__ constexpr float qp_cubic(int dn16) {   // t = |dn16|/16
    float t = (float)(dn16 < 0 ? -dn16 : dn16) / 16.0f;
    return (t < 1.0f) ? ((1.5f*t - 2.5f)*t)*t + 1.0f
         : (t < 2.0f) ? ((-0.5f*t + 2.5f)*t - 4.0f)*t + 2.0f
         : 0.0f;
}
__host__ __device__ constexpr float qp_wsum(int xo) {
    float s = 0.f;
    for (int k = qp_floor(xo) - 1; k <= qp_floor(xo) + 2; ++k)
        if (k >= 0 && k < HM) s += qp_cubic(14*xo - 1 - 16*k);
    return s;
}
__host__ __device__ constexpr float qp_wt(int xo, int slot) {
    int k = qp_base(xo) + slot;
    if (k < qp_floor(xo) - 1 || k > qp_floor(xo) + 2 || k < 0 || k >= HM)
        return 0.0f;
    return qp_cubic(14*xo - 1 - 16*k) * (1.0f / qp_wsum(xo));
}

// C++11-safe compile-time for.
template<int J, int N> struct SFor {
    template<typename F> __device__ __forceinline__ static void run(F&& f) {
        f(J_tag()); SFor<J+1, N>::run(f);
    }
    struct J_tag { static constexpr int value = J; };
};
template<int N> struct SFor<N, N> {
    template<typename F> __device__ __forceinline__ static void run(F&&) {}
};

// Interpolate 16 consecutive outputs (xo = 16Q..16Q+15) of one line.
// All weights are FFMA immediates.
template<int Q, typename F>
__device__ __forceinline__ void interp16(const float* __restrict__ row, F emit)
{
    float4 win4[qp_NL(Q)];
    #pragma unroll
    for (int i = 0; i < qp_NL(Q); i++)
        win4[i] = *(const float4*)(row + qp_W(Q) + 4*i);
    const float* win = (const float*)win4;
    SFor<0, 16>::run([&](auto jc) {
        constexpr int   j  = decltype(jc)::value;
        constexpr int   s  = qp_S(Q, j);
        constexpr int   xo = 16*Q + j;
        constexpr float w0 = qp_wt(xo, 0), w1 = qp_wt(xo, 1);
        constexpr float w2 = qp_wt(xo, 2), w3 = qp_wt(xo, 3);
        float v = fmaf(w0, win[s],
                  fmaf(w1, win[s+1],
                  fmaf(w2, win[s+2], w3 * win[s+3])));
        emit(j, v);
    });
}

// ---------------------------------------------------------------------------
// Keypoint multi-map block: 4 maps per CTA, cp.async single-buffer prefetch
// (stage 2 never reads smap, so the next map streams in behind it).
// 2 barriers/map: epilogue deferred past the refill barrier (parity swv/swi)
// and overlaps the next map's stage 1.
// ---------------------------------------------------------------------------
__device__ __forceinline__ void kp_multi(
    int map_base, const float* __restrict__ maps, const float* __restrict__ rois,
    float* __restrict__ out)
{
    __shared__ __align__(16) float smap[HM * SROW];   // 13440 B
    __shared__ __align__(16) float tmpT[RESO * SROW]; // 15360 B ([xo][y])
    __shared__ float swv[2][8];
    __shared__ int   swi[2][8];

    const int tid = threadIdx.x;
    const int lane_o = tid & 63;
    const int q      = tid >> 6;              // warp-uniform

    // Per-thread staging slots (idx < 784): dst smem offset, computed once.
    int  s_y0 = (tid)        / 14, s_c0 = (tid)        - s_y0 * 14;
    int  s_y1 = (tid + 256)  / 14, s_c1 = (tid + 256)  - s_y1 * 14;
    int  s_y2 = (tid + 512)  / 14, s_c2 = (tid + 512)  - s_y2 * 14;
    bool has3 = (tid + 768) < 784;            // tid < 16
    int  s_y3 = (tid + 768)  / 14, s_c3 = (tid + 768)  - s_y3 * 14;
    unsigned d0 = (unsigned)__cvta_generic_to_shared(smap + s_y0 * SROW + 4*s_c0);
    unsigned d1 = (unsigned)__cvta_generic_to_shared(smap + s_y1 * SROW + 4*s_c1);
    unsigned d2 = (unsigned)__cvta_generic_to_shared(smap + s_y2 * SROW + 4*s_c2);
    unsigned d3 = (unsigned)__cvta_generic_to_shared(smap + s_y3 * SROW + 4*s_c3);

    auto stage_load = [&](int mid) {
        const char* src = (const char*)(maps + (size_t)mid * (HM * HM));
        asm volatile("cp.async.cg.shared.global [%0], [%1], 16;"
                     :: "r"(d0), "l"(src + (size_t)tid * 16) : "memory");
        asm volatile("cp.async.cg.shared.global [%0], [%1], 16;"
                     :: "r"(d1), "l"(src + (size_t)(tid + 256) * 16) : "memory");
        asm volatile("cp.async.cg.shared.global [%0], [%1], 16;"
                     :: "r"(d2), "l"(src + (size_t)(tid + 512) * 16) : "memory");
        if (has3)
            asm volatile("cp.async.cg.shared.global [%0], [%1], 16;"
                         :: "r"(d3), "l"(src + (size_t)(tid + 768) * 16) : "memory");
        asm volatile("cp.async.commit_group;" ::: "memory");
    };

    stage_load(map_base);
    asm volatile("cp.async.wait_group 0;" ::: "memory");
    __syncthreads();

    #pragma unroll 1
    for (int m = 0; m < MAPS_PER_CTA; m++) {
        const int map_id = map_base + m;
        const int par = m & 1;

        // Stage 1: x-interp, transposed store tmpT[xo*SROW + y].
        if (lane_o < HM) {
            const float* row = smap + lane_o * SROW;
            float* tc = tmpT + lane_o;
            switch (q) {
            case 0: interp16<0>(row, [&](int j, float v){ tc[(   j)*SROW] = v; }); break;
            case 1: interp16<1>(row, [&](int j, float v){ tc[(16+j)*SROW] = v; }); break;
            case 2: interp16<2>(row, [&](int j, float v){ tc[(32+j)*SROW] = v; }); break;
            default:interp16<3>(row, [&](int j, float v){ tc[(48+j)*SROW] = v; }); break;
            }
        }
        __syncthreads();                       // tmpT ready; smap reads done

        // Prefetch next map into smap, hidden behind stage 2.
        if (m + 1 < MAPS_PER_CTA) stage_load(map_base + m + 1);

        // Stage 2: y-interp + fused argmax (track j only; p built once).
        float best = -INFINITY; int bj = 0;
        {
            const float* row = tmpT + lane_o * SROW;
            switch (q) {
            case 0: interp16<0>(row, [&](int j, float v){
                        if (v > best) { best = v; bj = j; } }); break;
            case 1: interp16<1>(row, [&](int j, float v){
                        if (v > best) { best = v; bj = j; } }); break;
            case 2: interp16<2>(row, [&](int j, float v){
                        if (v > best) { best = v; bj = j; } }); break;
            default:interp16<3>(row, [&](int j, float v){
                        if (v > best) { best = v; bj = j; } }); break;
            }
        }
        int bidx = ((16*q + bj) << 6) | lane_o;   // p = yo*64 + xo

        #pragma unroll
        for (int o = 16; o; o >>= 1) {
            float ov = __shfl_xor_sync(0xffffffffu, best, o);
            int   oi = __shfl_xor_sync(0xffffffffu, bidx, o);
            if (ov > best || (ov == best && oi < bidx)) { best = ov; bidx = oi; }
        }
        if ((tid & 31) == 0) { swv[par][tid >> 5] = best; swi[par][tid >> 5] = bidx; }

        asm volatile("cp.async.wait_group 0;" ::: "memory");
        __syncthreads();   // smap refilled; swv[par] visible; tmpT reusable

        // Deferred epilogue: overlaps next map's stage 1. Same-parity swv
        // write is 2 maps (2 barriers) away -> race-free.
        if (tid == 0) {
            #pragma unroll
            for (int i = 1; i < 8; i++) {
                if (swv[par][i] > best ||
                    (swv[par][i] == best && swi[par][i] < bidx)) {
                    best = swv[par][i]; bidx = swi[par][i];
                }
            }
            int r = map_id / K_KP;
            const float* rp = rois + r * 4;
            float x1 = rp[0], y1 = rp[1], x2 = rp[2], y2 = rp[3];
            float wc = fmaxf(x2 - x1, 1.f) * (1.f / (float)RESO);
            float hc = fmaxf(y2 - y1, 1.f) * (1.f / (float)RESO);
            int xi = bidx & 63, yi = bidx >> 6;
            float* xy = out + OFF_XY + (size_t)map_id * 3;
            xy[0] = (xi + 0.5f) * wc + x1;
            xy[1] = (yi + 0.5f) * hc + y1;
            xy[2] = 1.f;
            out[OFF_ES + map_id] = best;
        }
    }
}

// ---------------------------------------------------------------------------
// Mask inference: float4 gather, fast sigmoid, float2 stores (OFF_MASK is
// only 8B-aligned in the output).
// ---------------------------------------------------------------------------
__device__ __forceinline__ void mask_block(
    int mb, const float* __restrict__ mlog, const int* __restrict__ mlab,
    float* __restrict__ out)
{
    int idx = mb * 256 + threadIdx.x;          // float4 index < MASK_F4
    int r = idx / (MASK_HW / 4);
    int i = idx - r * (MASK_HW / 4);
    int lab = __ldg(&mlab[r]);
    float4 v = __ldg((const float4*)mlog + ((size_t)r * C_CLS + lab) * (MASK_HW / 4) + i);
    float2* o2 = (float2*)(out + OFF_MASK) + idx * 2;
    float2 a, b;
    a.x = __fdividef(1.f, 1.f + __expf(-v.x));
    a.y = __fdividef(1.f, 1.f + __expf(-v.y));
    b.x = __fdividef(1.f, 1.f + __expf(-v.z));
    b.y = __fdividef(1.f, 1.f + __expf(-v.w));
    o2[0] = a;
    o2[1] = b;
}

// ---------------------------------------------------------------------------
// FastRCNN loss partial block + last-block final reduction (deterministic).
// ---------------------------------------------------------------------------
__device__ __forceinline__ void loss_block(
    int lb, const float* __restrict__ logits, const float* __restrict__ br,
    const int* __restrict__ labels, const float* __restrict__ tgt,
    float* __restrict__ out)
{
    __shared__ float scls[8], sbox[8];
    __shared__ int   is_last;
    int lane  = threadIdx.x & 31;
    int wid   = threadIdx.x >> 5;
    int gwarp = lb * 8 + wid;
    const int nwarps = LOSS_BLOCKS * 8;

    float cls_acc = 0.f, box_acc = 0.f;
    for (int row = gwarp; row < N_ROWS; row += nwarps) {
        const float* lp = logits + (size_t)row * C_CLS;
        int lab = labels[row];
        float v0 = (lane      < C_CLS) ? lp[lane]      : -INFINITY;
        float v1 = (lane + 32 < C_CLS) ? lp[lane + 32] : -INFINITY;
        float v2 = (lane + 64 < C_CLS) ? lp[lane + 64] : -INFINITY;
        float m = fmaxf(v0, fmaxf(v1, v2));
        #pragma unroll
        for (int o = 16; o; o >>= 1) m = fmaxf(m, __shfl_xor_sync(0xffffffffu, m, o));
        float s = 0.f;
        if (lane      < C_CLS) s += __expf(v0 - m);
        if (lane + 32 < C_CLS) s += __expf(v1 - m);
        if (lane + 64 < C_CLS) s += __expf(v2 - m);
        #pragma unroll
        for (int o = 16; o; o >>= 1) s += __shfl_xor_sync(0xffffffffu, s, o);
        float lv = -INFINITY;
        if (lane == lab)           lv = v0;
        else if (lane + 32 == lab) lv = v1;
        else if (lane + 64 == lab) lv = v2;
        #pragma unroll
        for (int o = 16; o; o >>= 1) lv = fmaxf(lv, __shfl_xor_sync(0xffffffffu, lv, o));
        cls_acc += (m + __logf(s)) - lv;

        if (lab > 0) {
            float sl = 0.f;
            if (lane < 4) {
                float d  = br[(size_t)row * (C_CLS * 4) + lab * 4 + lane] - tgt[row * 4 + lane];
                float ad = fabsf(d);
                sl = (ad < BETA) ? 0.5f * d * d / BETA : ad - 0.5f * BETA;
            }
            sl += __shfl_xor_sync(0xffffffffu, sl, 1);
            sl += __shfl_xor_sync(0xffffffffu, sl, 2);
            if (lane == 0) box_acc += sl;
        }
    }

    if (lane == 0) { scls[wid] = cls_acc; sbox[wid] = box_acc; }
    __syncthreads();
    if (threadIdx.x == 0) {
        float c = 0.f, b = 0.f;
        #pragma unroll
        for (int i = 0; i < 8; i++) { c += scls[i]; b += sbox[i]; }
        g_partials[lb * 2]     = c;
        g_partials[lb * 2 + 1] = b;
        __threadfence();
        is_last = (atomicAdd(&g_done, 1) == LOSS_BLOCKS - 1);
    }
    __syncthreads();

    if (is_last && threadIdx.x < 32) {
        __threadfence();
        float c = 0.f, b = 0.f;
        for (int i = lane; i < LOSS_BLOCKS; i += 32) {
            c += g_partials[2 * i];
            b += g_partials[2 * i + 1];
        }
        #pragma unroll
        for (int o = 16; o; o >>= 1) {
            c += __shfl_xor_sync(0xffffffffu, c, o);
            b += __shfl_xor_sync(0xffffffffu, b, o);
        }
        if (lane == 0) {
            out[0] = c * (1.f / (float)N_ROWS);
            out[1] = b * (1.f / (float)N_ROWS);
            g_done = 0;                       // reset for next graph replay
        }
    }
}

// ---------------------------------------------------------------------------
// Fused kernel: loss first, then mask, then multi-map kp.
// ---------------------------------------------------------------------------
__global__ void __launch_bounds__(256) fused_kernel(
    const float* __restrict__ logits, const float* __restrict__ br,
    const int*   __restrict__ labels, const float* __restrict__ tgt,
    const float* __restrict__ kp_maps, const float* __restrict__ kp_rois,
    const float* __restrict__ mlog, const int* __restrict__ mlab,
    float* __restrict__ out)
{
    int b = blockIdx.x;
    if (b < LOSS_BLOCKS) {
        loss_block(b, logits, br, labels, tgt, out);
    } else if (b < LOSS_BLOCKS + MASK_BLOCKS) {
        mask_block(b - LOSS_BLOCKS, mlog, mlab, out);
    } else {
        kp_multi((b - (LOSS_BLOCKS + MASK_BLOCKS)) * MAPS_PER_CTA,
                 kp_maps, kp_rois, out);
    }
}

// ---------------------------------------------------------------------------
extern "C" void kernel_launch(void* const* d_in, const int* in_sizes, int n_in,
                              void* d_out, int out_size)
{
    const float* class_logits       = (const float*)d_in[0];
    const float* box_regression     = (const float*)d_in[1];
    const int*   labels             = (const int*)  d_in[2];
    const float* regression_targets = (const float*)d_in[3];
    const float* kp_maps            = (const float*)d_in[4];
    const float* kp_rois            = (const float*)d_in[5];
    const float* mask_logits        = (const float*)d_in[6];
    const int*   mask_labels        = (const int*)  d_in[7];
    float* out = (float*)d_out;

    fused_kernel<<<TOTAL_BLOCKS, 256>>>(class_logits, box_regression, labels,
                                        regression_targets, kp_maps, kp_rois,
                                        mask_logits, mask_labels, out);
}

// round 17
// speedup vs baseline: 1.1906x; 1.1197x over previous
#include <cuda_runtime.h>
#include <cstdint>
#include <math.h>

#define N_ROWS 4096
#define C_CLS  91
#define R_ROI  1024
#define K_KP   17
#define HM     56
#define RESO   64
#define BETA   (1.0f/9.0f)

#define OFF_XY   2
#define OFF_ES   (2 + R_ROI*K_KP*3)            /* 52226 */
#define OFF_MASK (OFF_ES + R_ROI*K_KP)         /* 69634 */
#define MASK_HW  784

#define MAPS_PER_CTA 4
#define KP_BLOCKS   (R_ROI * K_KP / MAPS_PER_CTA)  /* 4352 */
#define MASK_F4     (R_ROI * MASK_HW / 4)      /* 200704 float4 loads */
#define MASK_BLOCKS (MASK_F4 / 256)            /* 784 */
#define LOSS_BLOCKS 64
#define TOTAL_BLOCKS (LOSS_BLOCKS + MASK_BLOCKS + KP_BLOCKS)

#define SROW 60                                 /* padded row stride (floats) */

__device__ float g_partials[2 * LOSS_BLOCKS];
__device__ int   g_done = 0;

// ---------------------------------------------------------------------------
// Compile-time bicubic 56->64 resample parameters (jax.image.resize
// semantics: half-pixel sampling, Keys a=-0.5, OOB taps dropped + renorm).
// s(xo) = (14*xo - 1)/16 exactly.
// ---------------------------------------------------------------------------
__host__ __device__ constexpr int qp_floor(int xo) {
    int num = 14 * xo - 1;
    return (num >= 0) ? num / 16 : -((-num + 15) / 16);
}
__host__ __device__ constexpr int qp_base(int xo) {
    int b = qp_floor(xo) - 1;
    return (b < 0) ? 0 : ((b > HM - 4) ? (HM - 4) : b);
}
__host__ __device__ constexpr int qp_W(int Q)  { return Q==0?0 : Q==1?12 : Q==2?24 : 40; }
__host__ __device__ constexpr int qp_NL(int Q) { return (Q==1 || Q==2) ? 5 : 4; }
__host__ __device__ constexpr int qp_S(int Q, int j) { return qp_base(16*Q + j) - qp_W(Q); }

__host__ __device__ constexpr float qp_cubic(int dn16) {   // t = |dn16|/16
    float t = (float)(dn16 < 0 ? -dn16 : dn16) / 16.0f;
    return (t < 1.0f) ? ((1.5f*t - 2.5f)*t)*t + 1.0f
         : (t < 2.0f) ? ((-0.5f*t + 2.5f)*t - 4.0f)*t + 2.0f
         : 0.0f;
}
__host__ __device__ constexpr float qp_wsum(int xo) {
    float s = 0.f;
    for (int k = qp_floor(xo) - 1; k <= qp_floor(xo) + 2; ++k)
        if (k >= 0 && k < HM) s += qp_cubic(14*xo - 1 - 16*k);
    return s;
}
__host__ __device__ constexpr float qp_wt(int xo, int slot) {
    int k = qp_base(xo) + slot;
    if (k < qp_floor(xo) - 1 || k > qp_floor(xo) + 2 || k < 0 || k >= HM)
        return 0.0f;
    return qp_cubic(14*xo - 1 - 16*k) * (1.0f / qp_wsum(xo));
}

// C++11-safe compile-time for.
template<int J, int N> struct SFor {
    template<typename F> __device__ __forceinline__ static void run(F&& f) {
        f(J_tag()); SFor<J+1, N>::run(f);
    }
    struct J_tag { static constexpr int value = J; };
};
template<int N> struct SFor<N, N> {
    template<typename F> __device__ __forceinline__ static void run(F&&) {}
};

// Interpolate 16 consecutive outputs (xo = 16Q..16Q+15) of one line.
// All weights are FFMA immediates.
template<int Q, typename F>
__device__ __forceinline__ void interp16(const float* __restrict__ row, F emit)
{
    float4 win4[qp_NL(Q)];
    #pragma unroll
    for (int i = 0; i < qp_NL(Q); i++)
        win4[i] = *(const float4*)(row + qp_W(Q) + 4*i);
    const float* win = (const float*)win4;
    SFor<0, 16>::run([&](auto jc) {
        constexpr int   j  = decltype(jc)::value;
        constexpr int   s  = qp_S(Q, j);
        constexpr int   xo = 16*Q + j;
        constexpr float w0 = qp_wt(xo, 0), w1 = qp_wt(xo, 1);
        constexpr float w2 = qp_wt(xo, 2), w3 = qp_wt(xo, 3);
        float v = fmaf(w0, win[s],
                  fmaf(w1, win[s+1],
                  fmaf(w2, win[s+2], w3 * win[s+3])));
        emit(j, v);
    });
}

// ---------------------------------------------------------------------------
// Keypoint multi-map block: 4 maps per CTA, cp.async single-buffer prefetch
// (stage 2 never reads smap, so the next map streams in behind it).
// Warp argmax reduction via REDUX.SYNC (max on monotone key, min on index).
// ---------------------------------------------------------------------------
__device__ __forceinline__ void kp_multi(
    int map_base, const float* __restrict__ maps, const float* __restrict__ rois,
    float* __restrict__ out)
{
    __shared__ __align__(16) float smap[HM * SROW];   // 13440 B
    __shared__ __align__(16) float tmpT[RESO * SROW]; // 15360 B ([xo][y])
    __shared__ float swv[8];
    __shared__ int   swi[8];

    const int tid = threadIdx.x;
    const int lane_o = tid & 63;
    const int q      = tid >> 6;              // warp-uniform

    // Per-thread staging slots (idx < 784): dst smem offset, computed once.
    int  s_y0 = (tid)        / 14, s_c0 = (tid)        - s_y0 * 14;
    int  s_y1 = (tid + 256)  / 14, s_c1 = (tid + 256)  - s_y1 * 14;
    int  s_y2 = (tid + 512)  / 14, s_c2 = (tid + 512)  - s_y2 * 14;
    bool has3 = (tid + 768) < 784;            // tid < 16
    int  s_y3 = (tid + 768)  / 14, s_c3 = (tid + 768)  - s_y3 * 14;
    unsigned d0 = (unsigned)__cvta_generic_to_shared(smap + s_y0 * SROW + 4*s_c0);
    unsigned d1 = (unsigned)__cvta_generic_to_shared(smap + s_y1 * SROW + 4*s_c1);
    unsigned d2 = (unsigned)__cvta_generic_to_shared(smap + s_y2 * SROW + 4*s_c2);
    unsigned d3 = (unsigned)__cvta_generic_to_shared(smap + s_y3 * SROW + 4*s_c3);

    auto stage_load = [&](int mid) {
        const char* src = (const char*)(maps + (size_t)mid * (HM * HM));
        asm volatile("cp.async.cg.shared.global [%0], [%1], 16;"
                     :: "r"(d0), "l"(src + (size_t)tid * 16) : "memory");
        asm volatile("cp.async.cg.shared.global [%0], [%1], 16;"
                     :: "r"(d1), "l"(src + (size_t)(tid + 256) * 16) : "memory");
        asm volatile("cp.async.cg.shared.global [%0], [%1], 16;"
                     :: "r"(d2), "l"(src + (size_t)(tid + 512) * 16) : "memory");
        if (has3)
            asm volatile("cp.async.cg.shared.global [%0], [%1], 16;"
                         :: "r"(d3), "l"(src + (size_t)(tid + 768) * 16) : "memory");
        asm volatile("cp.async.commit_group;" ::: "memory");
    };

    stage_load(map_base);
    asm volatile("cp.async.wait_group 0;" ::: "memory");
    __syncthreads();

    #pragma unroll 1
    for (int m = 0; m < MAPS_PER_CTA; m++) {
        const int map_id = map_base + m;

        // Stage 1: x-interp, transposed store tmpT[xo*SROW + y].
        if (lane_o < HM) {
            const float* row = smap + lane_o * SROW;
            float* tc = tmpT + lane_o;
            switch (q) {
            case 0: interp16<0>(row, [&](int j, float v){ tc[(   j)*SROW] = v; }); break;
            case 1: interp16<1>(row, [&](int j, float v){ tc[(16+j)*SROW] = v; }); break;
            case 2: interp16<2>(row, [&](int j, float v){ tc[(32+j)*SROW] = v; }); break;
            default:interp16<3>(row, [&](int j, float v){ tc[(48+j)*SROW] = v; }); break;
            }
        }
        __syncthreads();                       // tmpT ready; smap reads done

        // Prefetch next map into smap, hidden behind stage 2.
        if (m + 1 < MAPS_PER_CTA) stage_load(map_base + m + 1);

        // Stage 2: y-interp + fused argmax (track j only; p built once).
        float best = -INFINITY; int bj = 0;
        {
            const float* row = tmpT + lane_o * SROW;
            switch (q) {
            case 0: interp16<0>(row, [&](int j, float v){
                        if (v > best) { best = v; bj = j; } }); break;
            case 1: interp16<1>(row, [&](int j, float v){
                        if (v > best) { best = v; bj = j; } }); break;
            case 2: interp16<2>(row, [&](int j, float v){
                        if (v > best) { best = v; bj = j; } }); break;
            default:interp16<3>(row, [&](int j, float v){
                        if (v > best) { best = v; bj = j; } }); break;
            }
        }
        int bidx = ((16*q + bj) << 6) | lane_o;   // p = yo*64 + xo

        // Warp reduction via REDUX: max on monotone key, then min index
        // among tied lanes; the unique winning lane writes the warp slot.
        {
            int t = __float_as_int(best);
            unsigned key  = (unsigned)t ^ (unsigned)((t >> 31) | 0x80000000);
            unsigned kmax = __reduce_max_sync(0xffffffffu, key);
            unsigned cand = (key == kmax) ? (unsigned)bidx : 0xffffffffu;
            unsigned bmin = __reduce_min_sync(0xffffffffu, cand);
            if (cand == bmin && key == kmax) {
                swv[tid >> 5] = best;
                swi[tid >> 5] = bidx;
            }
        }
        __syncthreads();                       // reduction bar

        if (tid == 0) {
            float bv = swv[0]; int bi = swi[0];
            #pragma unroll
            for (int i = 1; i < 8; i++) {
                if (swv[i] > bv || (swv[i] == bv && swi[i] < bi)) {
                    bv = swv[i]; bi = swi[i];
                }
            }
            int r = map_id / K_KP;
            const float* rp = rois + r * 4;
            float x1 = rp[0], y1 = rp[1], x2 = rp[2], y2 = rp[3];
            float wc = fmaxf(x2 - x1, 1.f) * (1.f / (float)RESO);
            float hc = fmaxf(y2 - y1, 1.f) * (1.f / (float)RESO);
            int xi = bi & 63, yi = bi >> 6;
            float* xy = out + OFF_XY + (size_t)map_id * 3;
            xy[0] = (xi + 0.5f) * wc + x1;
            xy[1] = (yi + 0.5f) * hc + y1;
            xy[2] = 1.f;
            out[OFF_ES + map_id] = bv;
        }

        asm volatile("cp.async.wait_group 0;" ::: "memory");
        __syncthreads();                       // smap refilled; swv/swi free
    }
}

// ---------------------------------------------------------------------------
// Mask inference: float4 gather, fast sigmoid, float2 stores (OFF_MASK is
// only 8B-aligned in the output).
// ---------------------------------------------------------------------------
__device__ __forceinline__ void mask_block(
    int mb, const float* __restrict__ mlog, const int* __restrict__ mlab,
    float* __restrict__ out)
{
    int idx = mb * 256 + threadIdx.x;          // float4 index < MASK_F4
    int r = idx / (MASK_HW / 4);
    int i = idx - r * (MASK_HW / 4);
    int lab = __ldg(&mlab[r]);
    float4 v = __ldg((const float4*)mlog + ((size_t)r * C_CLS + lab) * (MASK_HW / 4) + i);
    float2* o2 = (float2*)(out + OFF_MASK) + idx * 2;
    float2 a, b;
    a.x = __fdividef(1.f, 1.f + __expf(-v.x));
    a.y = __fdividef(1.f, 1.f + __expf(-v.y));
    b.x = __fdividef(1.f, 1.f + __expf(-v.z));
    b.y = __fdividef(1.f, 1.f + __expf(-v.w));
    o2[0] = a;
    o2[1] = b;
}

// ---------------------------------------------------------------------------
// FastRCNN loss partial block + last-block final reduction (deterministic).
// ---------------------------------------------------------------------------
__device__ __forceinline__ void loss_block(
    int lb, const float* __restrict__ logits, const float* __restrict__ br,
    const int* __restrict__ labels, const float* __restrict__ tgt,
    float* __restrict__ out)
{
    __shared__ float scls[8], sbox[8];
    __shared__ int   is_last;
    int lane  = threadIdx.x & 31;
    int wid   = threadIdx.x >> 5;
    int gwarp = lb * 8 + wid;
    const int nwarps = LOSS_BLOCKS * 8;

    float cls_acc = 0.f, box_acc = 0.f;
    for (int row = gwarp; row < N_ROWS; row += nwarps) {
        const float* lp = logits + (size_t)row * C_CLS;
        int lab = labels[row];
        float v0 = (lane      < C_CLS) ? lp[lane]      : -INFINITY;
        float v1 = (lane + 32 < C_CLS) ? lp[lane + 32] : -INFINITY;
        float v2 = (lane + 64 < C_CLS) ? lp[lane + 64] : -INFINITY;
        float m = fmaxf(v0, fmaxf(v1, v2));
        #pragma unroll
        for (int o = 16; o; o >>= 1) m = fmaxf(m, __shfl_xor_sync(0xffffffffu, m, o));
        float s = 0.f;
        if (lane      < C_CLS) s += __expf(v0 - m);
        if (lane + 32 < C_CLS) s += __expf(v1 - m);
        if (lane + 64 < C_CLS) s += __expf(v2 - m);
        #pragma unroll
        for (int o = 16; o; o >>= 1) s += __shfl_xor_sync(0xffffffffu, s, o);
        float lv = -INFINITY;
        if (lane == lab)           lv = v0;
        else if (lane + 32 == lab) lv = v1;
        else if (lane + 64 == lab) lv = v2;
        #pragma unroll
        for (int o = 16; o; o >>= 1) lv = fmaxf(lv, __shfl_xor_sync(0xffffffffu, lv, o));
        cls_acc += (m + __logf(s)) - lv;

        if (lab > 0) {
            float sl = 0.f;
            if (lane < 4) {
                float d  = br[(size_t)row * (C_CLS * 4) + lab * 4 + lane] - tgt[row * 4 + lane];
                float ad = fabsf(d);
                sl = (ad < BETA) ? 0.5f * d * d / BETA : ad - 0.5f * BETA;
            }
            sl += __shfl_xor_sync(0xffffffffu, sl, 1);
            sl += __shfl_xor_sync(0xffffffffu, sl, 2);
            if (lane == 0) box_acc += sl;
        }
    }

    if (lane == 0) { scls[wid] = cls_acc; sbox[wid] = box_acc; }
    __syncthreads();
    if (threadIdx.x == 0) {
        float c = 0.f, b = 0.f;
        #pragma unroll
        for (int i = 0; i < 8; i++) { c += scls[i]; b += sbox[i]; }
        g_partials[lb * 2]     = c;
        g_partials[lb * 2 + 1] = b;
        __threadfence();
        is_last = (atomicAdd(&g_done, 1) == LOSS_BLOCKS - 1);
    }
    __syncthreads();

    if (is_last && threadIdx.x < 32) {
        __threadfence();
        float c = 0.f, b = 0.f;
        for (int i = lane; i < LOSS_BLOCKS; i += 32) {
            c += g_partials[2 * i];
            b += g_partials[2 * i + 1];
        }
        #pragma unroll
        for (int o = 16; o; o >>= 1) {
            c += __shfl_xor_sync(0xffffffffu, c, o);
            b += __shfl_xor_sync(0xffffffffu, b, o);
        }
        if (lane == 0) {
            out[0] = c * (1.f / (float)N_ROWS);
            out[1] = b * (1.f / (float)N_ROWS);
            g_done = 0;                       // reset for next graph replay
        }
    }
}

// ---------------------------------------------------------------------------
// Fused kernel: loss first, then mask, then multi-map kp.
// ---------------------------------------------------------------------------
__global__ void __launch_bounds__(256) fused_kernel(
    const float* __restrict__ logits, const float* __restrict__ br,
    const int*   __restrict__ labels, const float* __restrict__ tgt,
    const float* __restrict__ kp_maps, const float* __restrict__ kp_rois,
    const float* __restrict__ mlog, const int* __restrict__ mlab,
    float* __restrict__ out)
{
    int b = blockIdx.x;
    if (b < LOSS_BLOCKS) {
        loss_block(b, logits, br, labels, tgt, out);
    } else if (b < LOSS_BLOCKS + MASK_BLOCKS) {
        mask_block(b - LOSS_BLOCKS, mlog, mlab, out);
    } else {
        kp_multi((b - (LOSS_BLOCKS + MASK_BLOCKS)) * MAPS_PER_CTA,
                 kp_maps, kp_rois, out);
    }
}

// ---------------------------------------------------------------------------
extern "C" void kernel_launch(void* const* d_in, const int* in_sizes, int n_in,
                              void* d_out, int out_size)
{
    const float* class_logits       = (const float*)d_in[0];
    const float* box_regression     = (const float*)d_in[1];
    const int*   labels             = (const int*)  d_in[2];
    const float* regression_targets = (const float*)d_in[3];
    const float* kp_maps            = (const float*)d_in[4];
    const float* kp_rois            = (const float*)d_in[5];
    const float* mask_logits        = (const float*)d_in[6];
    const int*   mask_labels        = (const int*)  d_in[7];
    float* out = (float*)d_out;

    fused_kernel<<<TOTAL_BLOCKS, 256>>>(class_logits, box_regression, labels,
                                        regression_targets, kp_maps, kp_rois,
                                        mask_logits, mask_labels, out);
}